// round 8
// baseline (speedup 1.0000x reference)
#include <cuda_runtime.h>

// Problem constants: B=64, D=2048, UNITS=1024, NW=64
#define Dd     2048
#define UNITSn 1024
#define NWn    64

#define UPC    8                 // units per CTA
#define NCTA   (UNITSn / UPC)    // 128 CTAs
#define BKt    128               // k-tile width
#define NT     (Dd / BKt)        // 16 tiles
#define NTHR   256               // 8 warps
#define NROW   8                 // batch rows per thread
#define RPAD   65                // reduce-buffer row stride (odd => spread banks)

__device__ __forceinline__ void fma2(unsigned long long& d,
                                     unsigned long long a,
                                     unsigned long long b) {
    asm("fma.rn.f32x2 %0, %1, %2, %0;" : "+l"(d) : "l"(a), "l"(b));
}
__device__ __forceinline__ unsigned mdiv(unsigned e, unsigned magic) {
    return (unsigned)(((unsigned long long)e * magic) >> 32);
}

// ---------------------------------------------------------------------------
// Fused hashed-linear, v2 of the direct-L2 design.
// Phase 1: build 8 dense W rows (8 x 2048 fp32, 64KB) in smem from the hashed
//          index lists (int4 loads, up to 16 LDG.128 in flight per thread).
// Phase 2: barrier-free GEMM. Warp z in [0,8) owns batch rows {z,z+8,...,z+56}
//          (8 rows/thread); lane owns k-offset 4*lane of each 128-wide k-tile.
//          x is read DIRECTLY from L2 via coalesced LDG.128 (1-tile pipeline,
//          tile-0 loads issued before phase 1 to hide their latency).
//          Each W LDS.128 feeds 16 fma2 (8 rows x 2) => L1wf == fma cycles.
// Epilogue: padded-smem cross-lane k-reduction + bias; no atomics.
// ---------------------------------------------------------------------------
__global__ __launch_bounds__(NTHR, 1) void fused_kernel(const float* __restrict__ x,
                                                        const float* __restrict__ w,
                                                        const float* __restrict__ bias,
                                                        const int* __restrict__ indices,
                                                        float* __restrict__ out,
                                                        int L, unsigned magicL) {
    extern __shared__ float sm[];
    float* ws  = sm;                 // [UPC][Dd] = 64KB (overlaid by reduce buf later)
    float* wsm = sm + UPC * Dd;      // [NWn]     (dead after phase 1)

    const int tid  = threadIdx.x;
    const int lane = tid & 31;
    const int z    = tid >> 5;                // warp id = row-group
    const int u0   = blockIdx.x * UPC;
    const int koff = lane * 4;                // this lane's k offset within a tile

    // Issue tile-0 x loads NOW; their L2/DRAM latency hides under phase 1.
    const float* xbase = x + (long)z * Dd + koff;   // row z; rows step by 8*Dd
    ulonglong2 xa[NROW];
    #pragma unroll
    for (int r = 0; r < NROW; r++)
        xa[r] = *(const ulonglong2*)(xbase + (long)r * 8 * Dd);

    // ---- Phase 1: build W rows in smem ----
    if (tid < NWn) wsm[tid] = w[tid];
    const float4 z4 = make_float4(0.f, 0.f, 0.f, 0.f);
    #pragma unroll
    for (int i = 0; i < 16; i++) ((float4*)ws)[i * NTHR + tid] = z4;  // zero 64KB
    __syncthreads();

    {
        const int NWL4 = 16 * L;                       // int4 count per unit
        const int4* ind4 = (const int4*)indices + (long)u0 * NWL4;
        int e4 = tid;
        // Paired iterations: 16 independent LDG.128 in flight.
        for (; e4 + NTHR < NWL4; e4 += 2 * NTHR) {
            int4 v[UPC], v2[UPC];
            #pragma unroll
            for (int uu = 0; uu < UPC; uu++) {
                v[uu]  = __ldg(ind4 + (long)uu * NWL4 + e4);
                v2[uu] = __ldg(ind4 + (long)uu * NWL4 + e4 + NTHR);
            }
            #pragma unroll
            for (int h = 0; h < 2; h++) {
                const int4* vv = h ? v2 : v;
                const int e = (e4 + h * NTHR) * 4;
                const unsigned k0 = mdiv(e,     magicL);
                const unsigned k1 = mdiv(e + 1, magicL);
                const unsigned k2 = mdiv(e + 2, magicL);
                const unsigned k3 = mdiv(e + 3, magicL);
                #pragma unroll
                for (int uu = 0; uu < UPC; uu++) {
                    float* wrow = ws + uu * Dd;
                    unsigned p;
                    p = (unsigned)(vv[uu].x - 1); if (p < (unsigned)Dd) wrow[p] = wsm[k0];
                    p = (unsigned)(vv[uu].y - 1); if (p < (unsigned)Dd) wrow[p] = wsm[k1];
                    p = (unsigned)(vv[uu].z - 1); if (p < (unsigned)Dd) wrow[p] = wsm[k2];
                    p = (unsigned)(vv[uu].w - 1); if (p < (unsigned)Dd) wrow[p] = wsm[k3];
                }
            }
        }
        for (; e4 < NWL4; e4 += NTHR) {
            int4 v[UPC];
            #pragma unroll
            for (int uu = 0; uu < UPC; uu++)
                v[uu] = __ldg(ind4 + (long)uu * NWL4 + e4);
            const int e = e4 * 4;
            const unsigned k0 = mdiv(e,     magicL);
            const unsigned k1 = mdiv(e + 1, magicL);
            const unsigned k2 = mdiv(e + 2, magicL);
            const unsigned k3 = mdiv(e + 3, magicL);
            #pragma unroll
            for (int uu = 0; uu < UPC; uu++) {
                float* wrow = ws + uu * Dd;
                unsigned p;
                p = (unsigned)(v[uu].x - 1); if (p < (unsigned)Dd) wrow[p] = wsm[k0];
                p = (unsigned)(v[uu].y - 1); if (p < (unsigned)Dd) wrow[p] = wsm[k1];
                p = (unsigned)(v[uu].z - 1); if (p < (unsigned)Dd) wrow[p] = wsm[k2];
                p = (unsigned)(v[uu].w - 1); if (p < (unsigned)Dd) wrow[p] = wsm[k3];
            }
        }
    }
    __syncthreads();   // ws ready; mainloop is barrier-free from here

    // ---- Phase 2: GEMM, x direct from L2, 64 independent f32x2 accumulators ----
    unsigned long long acc[NROW][UPC];
    #pragma unroll
    for (int r = 0; r < NROW; r++)
        #pragma unroll
        for (int j = 0; j < UPC; j++) acc[r][j] = 0ULL;    // (0.0f, 0.0f)

    #pragma unroll 2
    for (int t = 0; t < NT; t++) {
        // Software pipeline: issue next tile's 8 coalesced LDG.128 first.
        ulonglong2 xb[NROW];
        if (t + 1 < NT) {
            #pragma unroll
            for (int r = 0; r < NROW; r++)
                xb[r] = *(const ulonglong2*)(xbase + (long)r * 8 * Dd + (t + 1) * BKt);
        }

        const float* wk = ws + t * BKt + koff;
        #pragma unroll
        for (int j = 0; j < UPC; j++) {
            ulonglong2 wv = *(const ulonglong2*)(wk + j * Dd);   // conflict-free LDS.128
            #pragma unroll
            for (int r = 0; r < NROW; r++) {
                fma2(acc[r][j], xa[r].x, wv.x);   // k, k+1
                fma2(acc[r][j], xa[r].y, wv.y);   // k+2, k+3
            }
        }
        #pragma unroll
        for (int r = 0; r < NROW; r++) xa[r] = xb[r];
    }
    __syncthreads();   // all ws reads done; safe to overlay reduce buffer

    // ---- Epilogue: cross-lane k-reduction via padded smem, + bias ----
    float* red = sm;   // [256][RPAD] floats = 66.6KB (overlays ws + wsm)
    #pragma unroll
    for (int r = 0; r < NROW; r++)
        #pragma unroll
        for (int j = 0; j < UPC; j++) {
            unsigned long long v = acc[r][j];
            float s = __uint_as_float((unsigned)(v & 0xffffffffu)) +
                      __uint_as_float((unsigned)(v >> 32));
            red[(z * 32 + lane) * RPAD + r * UPC + j] = s;   // write: conflict-free
        }
    __syncthreads();

    // 512 outputs per CTA: o = (row, j); producing warp = row&7, slot = (row>>3)*8+j.
    #pragma unroll
    for (int o = tid; o < 64 * UPC; o += NTHR) {
        const int j   = o & 7;
        const int row = o >> 3;
        const int zz  = row & 7;
        const int i   = (row >> 3) * UPC + j;
        float s = 0.f;
        #pragma unroll
        for (int l = 0; l < 32; l++)
            s += red[(zz * 32 + l) * RPAD + i];
        s += __ldg(bias + u0 + j);
        out[(long)row * UNITSn + u0 + j] = s;
    }
}

// ---------------------------------------------------------------------------
extern "C" void kernel_launch(void* const* d_in, const int* in_sizes, int n_in,
                              void* d_out, int out_size) {
    const float* x       = (const float*)d_in[0];
    const float* w       = (const float*)d_in[1];
    const float* bias    = (const float*)d_in[2];
    const int*   indices = (const int*)d_in[3];
    float*       out     = (float*)d_out;

    const int L = in_sizes[3] / (UNITSn * NWn);
    const unsigned magicL =
        (unsigned)((0x100000000ULL + (unsigned long long)L - 1) / (unsigned long long)L);

    // smem = max(ws + wsm, reduce buffer) = 256*65 floats = 66,560 B
    const int smem_bytes = (NTHR * RPAD) * (int)sizeof(float);
    cudaFuncSetAttribute(fused_kernel, cudaFuncAttributeMaxDynamicSharedMemorySize,
                         smem_bytes);

    fused_kernel<<<NCTA, NTHR, smem_bytes>>>(x, w, bias, indices, out, L, magicL);
}

// round 9
// speedup vs baseline: 1.0190x; 1.0190x over previous
#include <cuda_runtime.h>

// Problem constants: B=64, D=2048, UNITS=1024, NW=64
#define Dd     2048
#define UNITSn 1024
#define NWn    64

#define UPC    8                 // units per CTA
#define NCTA   (UNITSn / UPC)    // 128 CTAs
#define BKt    64                // k-tile width (64 -> 8B operands, small live state)
#define NT     (Dd / BKt)        // 32 tiles
#define NTHR   256               // 8 warps
#define NROW   8                 // batch rows per thread
#define RPAD   65                // reduce-buffer row stride (odd => conflict-free)

__device__ __forceinline__ void fma2(unsigned long long& d,
                                     unsigned long long a,
                                     unsigned long long b) {
    asm("fma.rn.f32x2 %0, %1, %2, %0;" : "+l"(d) : "l"(a), "l"(b));
}
__device__ __forceinline__ unsigned mdiv(unsigned e, unsigned magic) {
    return (unsigned)(((unsigned long long)e * magic) >> 32);
}

// ---------------------------------------------------------------------------
// Fused hashed-linear, v3 of the direct-L2 design (R8 map, halved live state).
// Phase 1: build 8 dense W rows (8 x 2048 fp32, 64KB) in smem from the hashed
//          index lists (int4 loads, up to 16 LDG.128 in flight per thread).
// Phase 2: barrier-free GEMM. Warp z in [0,8) owns batch rows {z,z+8,...,z+56}
//          (8 rows/thread); lane owns k-offset 2*lane of each 64-wide k-tile.
//          x comes straight from L2 via coalesced LDG.64 with a 2-tile register
//          pipeline (tiles 0-1 issued before phase 1 to hide cold DRAM).
//          W comes from smem as conflict-free LDS.64; each W load feeds 8 fma2
//          (8 rows) => l1tex wavefronts == fma2 issue cycles (balanced pipes).
// Epilogue: padded-smem cross-lane k-reduction + bias; no atomics, 1 launch.
// ---------------------------------------------------------------------------
__global__ __launch_bounds__(NTHR, 1) void fused_kernel(const float* __restrict__ x,
                                                        const float* __restrict__ w,
                                                        const float* __restrict__ bias,
                                                        const int* __restrict__ indices,
                                                        float* __restrict__ out,
                                                        int L, unsigned magicL) {
    extern __shared__ float sm[];
    float* ws  = sm;                 // [UPC][Dd] = 64KB (overlaid by reduce buf later)
    float* wsm = sm + UPC * Dd;      // [NWn]     (dead after phase 1)

    const int tid  = threadIdx.x;
    const int lane = tid & 31;
    const int z    = tid >> 5;                // warp id = row-group (rows z+8r)
    const int u0   = blockIdx.x * UPC;
    const int koff = lane * 2;                // this lane's k offset within a tile

    // Issue tiles 0 and 1 of x NOW; their cold-DRAM latency hides under phase 1.
    const float* xb0 = x + (long)z * Dd + koff;     // row z; rows step by 8*Dd
    unsigned long long xa[NROW], xb[NROW];
    #pragma unroll
    for (int r = 0; r < NROW; r++) {
        xa[r] = *(const unsigned long long*)(xb0 + (long)r * 8 * Dd);
        xb[r] = *(const unsigned long long*)(xb0 + (long)r * 8 * Dd + BKt);
    }

    // ---- Phase 1: build W rows in smem ----
    if (tid < NWn) wsm[tid] = w[tid];
    const float4 z4 = make_float4(0.f, 0.f, 0.f, 0.f);
    #pragma unroll
    for (int i = 0; i < 16; i++) ((float4*)ws)[i * NTHR + tid] = z4;  // zero 64KB
    __syncthreads();

    {
        const int NWL4 = 16 * L;                       // int4 count per unit
        const int4* ind4 = (const int4*)indices + (long)u0 * NWL4;
        int e4 = tid;
        // Paired iterations: 16 independent LDG.128 in flight.
        for (; e4 + NTHR < NWL4; e4 += 2 * NTHR) {
            int4 v[UPC], v2[UPC];
            #pragma unroll
            for (int uu = 0; uu < UPC; uu++) {
                v[uu]  = __ldg(ind4 + (long)uu * NWL4 + e4);
                v2[uu] = __ldg(ind4 + (long)uu * NWL4 + e4 + NTHR);
            }
            #pragma unroll
            for (int h = 0; h < 2; h++) {
                const int4* vv = h ? v2 : v;
                const int e = (e4 + h * NTHR) * 4;
                const unsigned k0 = mdiv(e,     magicL);
                const unsigned k1 = mdiv(e + 1, magicL);
                const unsigned k2 = mdiv(e + 2, magicL);
                const unsigned k3 = mdiv(e + 3, magicL);
                #pragma unroll
                for (int uu = 0; uu < UPC; uu++) {
                    float* wrow = ws + uu * Dd;
                    unsigned p;
                    p = (unsigned)(vv[uu].x - 1); if (p < (unsigned)Dd) wrow[p] = wsm[k0];
                    p = (unsigned)(vv[uu].y - 1); if (p < (unsigned)Dd) wrow[p] = wsm[k1];
                    p = (unsigned)(vv[uu].z - 1); if (p < (unsigned)Dd) wrow[p] = wsm[k2];
                    p = (unsigned)(vv[uu].w - 1); if (p < (unsigned)Dd) wrow[p] = wsm[k3];
                }
            }
        }
        for (; e4 < NWL4; e4 += NTHR) {
            int4 v[UPC];
            #pragma unroll
            for (int uu = 0; uu < UPC; uu++)
                v[uu] = __ldg(ind4 + (long)uu * NWL4 + e4);
            const int e = e4 * 4;
            const unsigned k0 = mdiv(e,     magicL);
            const unsigned k1 = mdiv(e + 1, magicL);
            const unsigned k2 = mdiv(e + 2, magicL);
            const unsigned k3 = mdiv(e + 3, magicL);
            #pragma unroll
            for (int uu = 0; uu < UPC; uu++) {
                float* wrow = ws + uu * Dd;
                unsigned p;
                p = (unsigned)(v[uu].x - 1); if (p < (unsigned)Dd) wrow[p] = wsm[k0];
                p = (unsigned)(v[uu].y - 1); if (p < (unsigned)Dd) wrow[p] = wsm[k1];
                p = (unsigned)(v[uu].z - 1); if (p < (unsigned)Dd) wrow[p] = wsm[k2];
                p = (unsigned)(v[uu].w - 1); if (p < (unsigned)Dd) wrow[p] = wsm[k3];
            }
        }
    }
    __syncthreads();   // ws ready; mainloop is barrier-free from here

    // ---- Phase 2: GEMM, x direct from L2, 2-tile register pipeline ----
    unsigned long long acc[NROW][UPC];
    #pragma unroll
    for (int r = 0; r < NROW; r++)
        #pragma unroll
        for (int j = 0; j < UPC; j++) acc[r][j] = 0ULL;    // (0.0f, 0.0f)

    #pragma unroll 4
    for (int t = 0; t < NT; t++) {
        // Issue tile t+2's 8 coalesced LDG.64 first (2-tile lookahead).
        unsigned long long xc[NROW];
        if (t + 2 < NT) {
            #pragma unroll
            for (int r = 0; r < NROW; r++)
                xc[r] = *(const unsigned long long*)(xb0 + (long)r * 8 * Dd
                                                     + (t + 2) * BKt);
        }

        // Batch all 8 W LDS.64 (independent), then the 64 fma2.
        unsigned long long wv[UPC];
        const float* wk = ws + t * BKt + koff;
        #pragma unroll
        for (int j = 0; j < UPC; j++)
            wv[j] = *(const unsigned long long*)(wk + j * Dd);  // conflict-free LDS.64

        #pragma unroll
        for (int j = 0; j < UPC; j++)
            #pragma unroll
            for (int r = 0; r < NROW; r++)
                fma2(acc[r][j], xa[r], wv[j]);

        #pragma unroll
        for (int r = 0; r < NROW; r++) { xa[r] = xb[r]; xb[r] = xc[r]; }
    }
    __syncthreads();   // all ws reads done; safe to overlay reduce buffer

    // ---- Epilogue: cross-lane k-reduction via padded smem, + bias ----
    float* red = sm;   // [256][RPAD] floats = 66.6KB (overlays ws + wsm)
    #pragma unroll
    for (int r = 0; r < NROW; r++)
        #pragma unroll
        for (int j = 0; j < UPC; j++) {
            unsigned long long v = acc[r][j];
            float s = __uint_as_float((unsigned)(v & 0xffffffffu)) +
                      __uint_as_float((unsigned)(v >> 32));
            red[(z * 32 + lane) * RPAD + r * UPC + j] = s;   // write: conflict-free
        }
    __syncthreads();

    // 512 outputs per CTA: row = o>>3 (owner warp = row&7), slot = (row>>3)*8+j.
    #pragma unroll
    for (int o = tid; o < 64 * UPC; o += NTHR) {
        const int j   = o & 7;
        const int row = o >> 3;
        const int zz  = row & 7;
        const int i   = (row >> 3) * UPC + j;
        float s = 0.f;
        #pragma unroll
        for (int l = 0; l < 32; l++)
            s += red[(zz * 32 + l) * RPAD + i];
        s += __ldg(bias + u0 + j);
        out[(long)row * UNITSn + u0 + j] = s;
    }
}

// ---------------------------------------------------------------------------
extern "C" void kernel_launch(void* const* d_in, const int* in_sizes, int n_in,
                              void* d_out, int out_size) {
    const float* x       = (const float*)d_in[0];
    const float* w       = (const float*)d_in[1];
    const float* bias    = (const float*)d_in[2];
    const int*   indices = (const int*)d_in[3];
    float*       out     = (float*)d_out;

    const int L = in_sizes[3] / (UNITSn * NWn);
    const unsigned magicL =
        (unsigned)((0x100000000ULL + (unsigned long long)L - 1) / (unsigned long long)L);

    // smem = max(ws + wsm, reduce buffer) = 256*65 floats = 66,560 B
    const int smem_bytes = (NTHR * RPAD) * (int)sizeof(float);
    cudaFuncSetAttribute(fused_kernel, cudaFuncAttributeMaxDynamicSharedMemorySize,
                         smem_bytes);

    fused_kernel<<<NCTA, NTHR, smem_bytes>>>(x, w, bias, indices, out, L, magicL);
}